// round 8
// baseline (speedup 1.0000x reference)
#include <cuda_runtime.h>
#include <math.h>

#define N_EDGES 100000
#define N_ATOMS 10000
#define UNC_W   1280   // sum over l of 3^l * 32 = 32+96+288+864
#define CAT_W   960

// uncoupled-space per-atom features and pooled scatter target (both ~51.2MB, L2-resident)
__device__ __align__(16) float g_uncF[(size_t)N_ATOMS * UNC_W];
__device__ __align__(16) float g_pool[(size_t)N_ATOMS * UNC_W];

// ---------------------------------------------------------------------------
// helpers (branchless select chains; avoid local-memory arrays)
// ---------------------------------------------------------------------------
__device__ __forceinline__ int sel4(int l, int a, int b, int c, int d) {
    return l == 0 ? a : (l == 1 ? b : (l == 2 ? c : d));
}
__device__ __forceinline__ const float* selp(int l, const float* a, const float* b,
                                             const float* c, const float* d) {
    return l == 0 ? a : (l == 1 ? b : (l == 2 ? c : d));
}

__device__ __forceinline__ void red_add_v4(float* addr, float x, float y, float z, float w) {
    asm volatile("red.global.add.v4.f32 [%0], {%1,%2,%3,%4};"
                 :: "l"(addr), "f"(x), "f"(y), "f"(z), "f"(w) : "memory");
}

// ---------------------------------------------------------------------------
// K_zero: clear pooled accumulator
// ---------------------------------------------------------------------------
__global__ void k_zero() {
    size_t i = (size_t)blockIdx.x * blockDim.x + threadIdx.x;
    const size_t n4 = (size_t)N_ATOMS * UNC_W / 4;
    float4 z = make_float4(0.f, 0.f, 0.f, 0.f);
    for (size_t u = i; u < n4; u += (size_t)gridDim.x * blockDim.x)
        reinterpret_cast<float4*>(g_pool)[u] = z;
}

// ---------------------------------------------------------------------------
// K_uncF: per-atom uncouple of features.
// unc_f[l][d,k] = sum_{lp<=l} sum_m U_l[d, lp^2+m] * feat_lp[n, m, lo_l + k]
// layout: g_uncF[n*1280 + F_OFF[l] + d*32 + k], F_OFF={0,32,128,416}
// ---------------------------------------------------------------------------
__global__ __launch_bounds__(128) void k_uncf(
    const float* __restrict__ f0, const float* __restrict__ f1,
    const float* __restrict__ f2, const float* __restrict__ f3,
    const float* __restrict__ U0, const float* __restrict__ U1,
    const float* __restrict__ U2, const float* __restrict__ U3)
{
    __shared__ float fb[CAT_W];  // all feat rows of this atom: offsets {0,128,416,736}
    const int n = blockIdx.x;
    const int t = threadIdx.x;

    // cooperative float4 copy of feat[n] (sizes 128,288,320,224 floats)
    for (int u = t; u < 240; u += 128) {
        int l    = (u >= 184) ? 3 : (u >= 104) ? 2 : (u >= 32) ? 1 : 0;
        int off4 = u - sel4(l, 0, 32, 104, 184);
        int row  = sel4(l, 128, 288, 320, 224);
        const float* src = selp(l, f0, f1, f2, f3) + (size_t)n * row;
        float4 v = __ldg(reinterpret_cast<const float4*>(src + off4 * 4));
        *reinterpret_cast<float4*>(&fb[sel4(l, 0, 128, 416, 736) + off4 * 4]) = v;
    }
    __syncthreads();

    float* dst = g_uncF + (size_t)n * UNC_W;
    for (int v = t; v < UNC_W; v += 128) {
        int l   = (v >= 416) ? 3 : (v >= 128) ? 2 : (v >= 32) ? 1 : 0;
        int idx = v - sel4(l, 0, 32, 128, 416);
        int d   = idx >> 5;
        int k   = idx & 31;
        int lo  = sel4(l, 96, 64, 32, 0);
        const float* Ul = selp(l, U0, U1, U2, U3);
        int L1 = (l + 1) * (l + 1);
        float acc = 0.f;
        #pragma unroll
        for (int lp = 0; lp <= 3; lp++) {
            if (lp > l) break;
            int fboff = sel4(lp, 0, 128, 416, 736);
            int w     = sel4(lp, 128, 96, 64, 32);
            int ub    = 2 * lp + 1;
            int ubase = d * L1 + lp * lp;
            for (int m = 0; m < ub; m++)
                acc += __ldg(&Ul[ubase + m]) * fb[fboff + m * w + lo + k];
        }
        dst[v] = acc;
    }
}

// ---------------------------------------------------------------------------
// K_edge: fused radial + coupling coefficients + gather + multiply + scatter.
// One warp per edge, 8 warps/block.
// ---------------------------------------------------------------------------
__global__ __launch_bounds__(256) void k_edge(
    const float* __restrict__ r,
    const float* __restrict__ sh0, const float* __restrict__ sh1,
    const float* __restrict__ sh2, const float* __restrict__ sh3,
    const float* __restrict__ Wr0, const float* __restrict__ Wr1,
    const float* __restrict__ Wr2, const float* __restrict__ Wr3,
    const float* __restrict__ U0, const float* __restrict__ U1,
    const float* __restrict__ U2, const float* __restrict__ U3,
    const int* __restrict__ centers, const int* __restrict__ neighbors)
{
    __shared__ float s_sh[8][16];
    __shared__ float s_rb[8][8];
    __shared__ float s_rad[8][320];   // radial_lp full rows: offsets {0,128,224,288}
    __shared__ float s_cc[8][144];    // c_l[d,lp] coeffs: offsets {0,1,7,34}, 142 used

    const int wid  = threadIdx.x >> 5;
    const int lane = threadIdx.x & 31;
    const int e    = blockIdx.x * 8 + wid;
    if (e >= N_EDGES) return;

    const float rv = __ldg(&r[e]);

    // spherical-harmonic values for this edge (16 floats)
    if (lane < 16) {
        float v;
        if (lane == 0)      v = __ldg(&sh0[e]);
        else if (lane < 4)  v = __ldg(&sh1[(size_t)e * 3 + (lane - 1)]);
        else if (lane < 9)  v = __ldg(&sh2[(size_t)e * 5 + (lane - 4)]);
        else                v = __ldg(&sh3[(size_t)e * 7 + (lane - 9)]);
        s_sh[wid][lane] = v;
    }
    // radial basis (8 values) with smooth cutoff
    if (lane < 8) {
        const float PI = 3.14159265358979323846f;
        float fc = 0.5f * (cosf(PI * fminf(rv * 0.2f, 1.0f)) + 1.0f);
        float a  = rv * (PI * 0.2f);
        s_rb[wid][lane] = sinf((float)(lane + 1) * a) / (rv + 1e-6f) * fc;
    }
    __syncwarp();

    // radial[lp][c] = rb . Wrad_lp[:,c], all 320 values
    for (int t = lane; t < 320; t += 32) {
        int lp = (t >= 288) ? 3 : (t >= 224) ? 2 : (t >= 128) ? 1 : 0;
        int c  = t - sel4(lp, 0, 128, 224, 288);
        int w  = sel4(lp, 128, 96, 64, 32);
        const float* W = selp(lp, Wr0, Wr1, Wr2, Wr3);
        float acc = 0.f;
        #pragma unroll
        for (int i = 0; i < 8; i++)
            acc += s_rb[wid][i] * __ldg(&W[i * w + c]);
        s_rad[wid][t] = acc;
    }
    // c_l[d,lp] = sum_m U_l[d, lp^2+m] * sh_lp[m]   (142 values)
    for (int t = lane; t < 142; t += 32) {
        int l   = (t >= 34) ? 3 : (t >= 7) ? 2 : (t >= 1) ? 1 : 0;
        int rem = t - sel4(l, 0, 1, 7, 34);
        int d   = rem / (l + 1);
        int lp  = rem - d * (l + 1);
        const float* Ul = selp(l, U0, U1, U2, U3);
        int ubase = d * (l + 1) * (l + 1) + lp * lp;
        int shoff = lp * lp;   // {0,1,4,9}
        float acc = 0.f;
        int ub = 2 * lp + 1;
        for (int m = 0; m < ub; m++)
            acc += __ldg(&Ul[ubase + m]) * s_sh[wid][shoff + m];
        s_cc[wid][t] = acc;
    }
    __syncwarp();

    const int ctr = __ldg(&centers[e]);
    const int nb  = __ldg(&neighbors[e]);
    const float* fN = g_uncF + (size_t)nb  * UNC_W;
    float*       pC = g_pool + (size_t)ctr * UNC_W;

    #pragma unroll
    for (int j = 0; j < 10; j++) {
        int u  = lane + 32 * j;
        int cbc = u * 4;
        int l  = (cbc >= 416) ? 3 : (cbc >= 128) ? 2 : (cbc >= 32) ? 1 : 0;
        int idx = cbc - sel4(l, 0, 32, 128, 416);
        int d   = idx >> 5;
        int k0  = idx & 31;
        int lo  = sel4(l, 96, 64, 32, 0);

        float4 f4 = __ldg(reinterpret_cast<const float4*>(fN + cbc));

        float u0 = 0.f, u1 = 0.f, u2 = 0.f, u3 = 0.f;
        const float* ccp = &s_cc[wid][sel4(l, 0, 1, 7, 34) + d * (l + 1)];
        #pragma unroll
        for (int lp = 0; lp <= 3; lp++) {
            if (lp > l) break;
            float c = ccp[lp];
            const float* rp = &s_rad[wid][sel4(lp, 0, 128, 224, 288) + lo + k0];
            u0 += c * rp[0]; u1 += c * rp[1]; u2 += c * rp[2]; u3 += c * rp[3];
        }
        red_add_v4(pC + cbc, u0 * f4.x, u1 * f4.y, u2 * f4.z, u3 * f4.w);
    }
}

// ---------------------------------------------------------------------------
// K_out: couple pooled back, build cat, Wlin GEMM + residual.
// One block (128 thr) per atom.
// ---------------------------------------------------------------------------
__global__ __launch_bounds__(128) void k_out(
    const float* __restrict__ U0, const float* __restrict__ U1,
    const float* __restrict__ U2, const float* __restrict__ U3,
    const float* __restrict__ W0, const float* __restrict__ W1,
    const float* __restrict__ W2, const float* __restrict__ W3,
    const float* __restrict__ f0, const float* __restrict__ f1,
    const float* __restrict__ f2, const float* __restrict__ f3,
    float* __restrict__ out)
{
    __shared__ float pb[UNC_W];
    __shared__ float cb[CAT_W];   // cat layout: offsets {0,128,416,736}, row width KMAX[l]
    const int n = blockIdx.x;
    const int t = threadIdx.x;

    // load pooled[n]
    {
        const float4* src = reinterpret_cast<const float4*>(g_pool + (size_t)n * UNC_W);
        for (int u = t; u < UNC_W / 4; u += 128)
            reinterpret_cast<float4*>(pb)[u] = src[u];
    }
    __syncthreads();

    // couple:  x_lp[mm,k] = sum_d U_lp[d,mm] * pooled[lp][d,k]  -> scatter into cat layout
    for (int v = t; v < CAT_W; v += 128) {
        int lp  = (v >= 448) ? 3 : (v >= 160) ? 2 : (v >= 32) ? 1 : 0;
        int rem = v - sel4(lp, 0, 32, 160, 448);
        int mm  = rem >> 5;
        int k   = rem & 31;
        const float* Ul = selp(lp, U0, U1, U2, U3);
        int L1 = (lp + 1) * (lp + 1);
        int D  = sel4(lp, 1, 3, 9, 27);
        int pof = sel4(lp, 0, 32, 128, 416);
        float acc = 0.f;
        for (int d = 0; d < D; d++)
            acc += __ldg(&Ul[d * L1 + mm]) * pb[pof + d * 32 + k];
        int l = (mm >= 9) ? 3 : (mm >= 4) ? 2 : (mm >= 1) ? 1 : 0;
        int m = mm - l * l;
        int K = sel4(l, 128, 96, 64, 32);
        cb[sel4(l, 0, 128, 416, 736) + m * K + (lp - l) * 32 + k] = acc;
    }
    __syncthreads();

    // out[l][m,q] = feat_l[n][m,q] + sum_kk cat[l][m,kk] * Wlin_l[kk,q]
    for (int w = t; w < 240; w += 128) {
        int l   = (w >= 184) ? 3 : (w >= 104) ? 2 : (w >= 32) ? 1 : 0;
        int rem = w - sel4(l, 0, 32, 104, 184);
        int K   = sel4(l, 128, 96, 64, 32);
        int qw  = K >> 2;
        int m   = rem / qw;
        int q4  = (rem - m * qw) * 4;
        const float* Wl   = selp(l, W0, W1, W2, W3);
        const float* crow = &cb[sel4(l, 0, 128, 416, 736) + m * K];
        int nrows = 2 * l + 1;
        const float* frow = selp(l, f0, f1, f2, f3) + (size_t)n * nrows * K + m * K + q4;
        float4 acc = __ldg(reinterpret_cast<const float4*>(frow));
        #pragma unroll 4
        for (int kk = 0; kk < K; kk++) {
            float a  = crow[kk];
            float4 wv = __ldg(reinterpret_cast<const float4*>(&Wl[kk * K + q4]));
            acc.x += a * wv.x; acc.y += a * wv.y; acc.z += a * wv.z; acc.w += a * wv.w;
        }
        size_t obase = sel4(l, 0, 1280000, 4160000, 7360000);
        float* op = out + obase + (size_t)n * nrows * K + m * K + q4;
        *reinterpret_cast<float4*>(op) = acc;
    }
}

// ---------------------------------------------------------------------------
// kernel_launch: robust input binding.
// setup_inputs() builds its dict INTERLEAVED per l: r, [sh_l, feat_l, Wrad_l,
// U_l, Wlin_l for l=0..3], centers, neighbors. The reference signature is
// GROUPED: r, sh0..3, feat0..3, Wrad0..3, U0..3, Wlin0..3, centers, neighbors.
// metadata.txt could also be alphabetical by key. Detect via in_sizes:
//   in_sizes[0] == 1        -> alphabetical (U0 first, 1 element)
//   in_sizes[2] == 1280000  -> interleaved  (feat0 at index 2)
//   in_sizes[2] == 300000   -> grouped      (sh1 at index 2)
// ---------------------------------------------------------------------------
extern "C" void kernel_launch(void* const* d_in, const int* in_sizes, int n_in,
                              void* d_out, int out_size)
{
    int I_r, I_sh[4], I_f[4], I_Wr[4], I_U[4], I_Wl[4], I_c, I_nb;

    if (in_sizes[0] == 1) {
        // alphabetical: U0-3, Wlin0-3, Wrad0-3, centers, feat0-3, neighbors, r, sh0-3
        for (int l = 0; l < 4; l++) { I_U[l] = l; I_Wl[l] = 4 + l; I_Wr[l] = 8 + l; }
        I_c = 12;
        for (int l = 0; l < 4; l++) I_f[l] = 13 + l;
        I_nb = 17; I_r = 18;
        for (int l = 0; l < 4; l++) I_sh[l] = 19 + l;
    } else if (in_sizes[2] == 1280000) {
        // interleaved dict order
        I_r = 0;
        for (int l = 0; l < 4; l++) {
            I_sh[l] = 1 + 5 * l; I_f[l]  = 2 + 5 * l; I_Wr[l] = 3 + 5 * l;
            I_U[l]  = 4 + 5 * l; I_Wl[l] = 5 + 5 * l;
        }
        I_c = 21; I_nb = 22;
    } else {
        // grouped (reference signature) order
        I_r = 0;
        for (int l = 0; l < 4; l++) {
            I_sh[l] = 1 + l; I_f[l] = 5 + l; I_Wr[l] = 9 + l;
            I_U[l] = 13 + l; I_Wl[l] = 17 + l;
        }
        I_c = 21; I_nb = 22;
    }

    const float* r   = (const float*)d_in[I_r];
    const float* sh0 = (const float*)d_in[I_sh[0]];
    const float* sh1 = (const float*)d_in[I_sh[1]];
    const float* sh2 = (const float*)d_in[I_sh[2]];
    const float* sh3 = (const float*)d_in[I_sh[3]];
    const float* f0  = (const float*)d_in[I_f[0]];
    const float* f1  = (const float*)d_in[I_f[1]];
    const float* f2  = (const float*)d_in[I_f[2]];
    const float* f3  = (const float*)d_in[I_f[3]];
    const float* Wr0 = (const float*)d_in[I_Wr[0]];
    const float* Wr1 = (const float*)d_in[I_Wr[1]];
    const float* Wr2 = (const float*)d_in[I_Wr[2]];
    const float* Wr3 = (const float*)d_in[I_Wr[3]];
    const float* U0  = (const float*)d_in[I_U[0]];
    const float* U1  = (const float*)d_in[I_U[1]];
    const float* U2  = (const float*)d_in[I_U[2]];
    const float* U3  = (const float*)d_in[I_U[3]];
    const float* W0  = (const float*)d_in[I_Wl[0]];
    const float* W1  = (const float*)d_in[I_Wl[1]];
    const float* W2  = (const float*)d_in[I_Wl[2]];
    const float* W3  = (const float*)d_in[I_Wl[3]];
    const int* centers   = (const int*)d_in[I_c];
    const int* neighbors = (const int*)d_in[I_nb];
    float* out = (float*)d_out;

    k_zero<<<512, 256>>>();
    k_uncf<<<N_ATOMS, 128>>>(f0, f1, f2, f3, U0, U1, U2, U3);
    k_edge<<<(N_EDGES + 7) / 8, 256>>>(r, sh0, sh1, sh2, sh3,
                                       Wr0, Wr1, Wr2, Wr3,
                                       U0, U1, U2, U3, centers, neighbors);
    k_out<<<N_ATOMS, 128>>>(U0, U1, U2, U3, W0, W1, W2, W3,
                            f0, f1, f2, f3, out);
}

// round 11
// speedup vs baseline: 1.1126x; 1.1126x over previous
#include <cuda_runtime.h>
#include <math.h>

#define N_EDGES 100000
#define N_ATOMS 10000
#define UNC_W   1280   // sum over l of 3^l * 32 = 32+96+288+864
#define CAT_W   960

// uncoupled-space per-atom features and pooled scatter target (both ~51.2MB, L2-resident)
__device__ __align__(16) float g_uncF[(size_t)N_ATOMS * UNC_W];
__device__ __align__(16) float g_pool[(size_t)N_ATOMS * UNC_W];
// cat scratch reuses g_uncF (k_edge has finished reading it before k_couple writes)
#define g_cat g_uncF

// ---------------------------------------------------------------------------
// helpers (branchless select chains; avoid local-memory arrays)
// ---------------------------------------------------------------------------
__device__ __forceinline__ int sel4(int l, int a, int b, int c, int d) {
    return l == 0 ? a : (l == 1 ? b : (l == 2 ? c : d));
}
__device__ __forceinline__ const float* selp(int l, const float* a, const float* b,
                                             const float* c, const float* d) {
    return l == 0 ? a : (l == 1 ? b : (l == 2 ? c : d));
}

__device__ __forceinline__ void red_add_v4(float* addr, float x, float y, float z, float w) {
    asm volatile("red.global.add.v4.f32 [%0], {%1,%2,%3,%4};"
                 :: "l"(addr), "f"(x), "f"(y), "f"(z), "f"(w) : "memory");
}

// ---------------------------------------------------------------------------
// K_uncF: per-atom uncouple of features (+ fused zeroing of g_pool row).
// unc_f[l][d,k] = sum_{lp<=l} sum_m U_l[d, lp^2+m] * feat_lp[n, m, lo_l + k]
// layout: g_uncF[n*1280 + F_OFF[l] + d*32 + k], F_OFF={0,32,128,416}
// ---------------------------------------------------------------------------
__global__ __launch_bounds__(128) void k_uncf(
    const float* __restrict__ f0, const float* __restrict__ f1,
    const float* __restrict__ f2, const float* __restrict__ f3,
    const float* __restrict__ U0, const float* __restrict__ U1,
    const float* __restrict__ U2, const float* __restrict__ U3)
{
    __shared__ float fb[CAT_W];  // all feat rows of this atom: offsets {0,128,416,736}
    const int n = blockIdx.x;
    const int t = threadIdx.x;

    // fused: zero this atom's pooled accumulator row (320 float4 = 1280 floats)
    {
        float4 z = make_float4(0.f, 0.f, 0.f, 0.f);
        float4* pz = reinterpret_cast<float4*>(g_pool + (size_t)n * UNC_W);
        for (int u = t; u < UNC_W / 4; u += 128) pz[u] = z;
    }

    // cooperative float4 copy of feat[n] (sizes 128,288,320,224 floats)
    for (int u = t; u < 240; u += 128) {
        int l    = (u >= 184) ? 3 : (u >= 104) ? 2 : (u >= 32) ? 1 : 0;
        int off4 = u - sel4(l, 0, 32, 104, 184);
        int row  = sel4(l, 128, 288, 320, 224);
        const float* src = selp(l, f0, f1, f2, f3) + (size_t)n * row;
        float4 v = __ldg(reinterpret_cast<const float4*>(src + off4 * 4));
        *reinterpret_cast<float4*>(&fb[sel4(l, 0, 128, 416, 736) + off4 * 4]) = v;
    }
    __syncthreads();

    float* dst = g_uncF + (size_t)n * UNC_W;
    for (int v = t; v < UNC_W; v += 128) {
        int l   = (v >= 416) ? 3 : (v >= 128) ? 2 : (v >= 32) ? 1 : 0;
        int idx = v - sel4(l, 0, 32, 128, 416);
        int d   = idx >> 5;
        int k   = idx & 31;
        int lo  = sel4(l, 96, 64, 32, 0);
        const float* Ul = selp(l, U0, U1, U2, U3);
        int L1 = (l + 1) * (l + 1);
        float acc = 0.f;
        #pragma unroll
        for (int lp = 0; lp <= 3; lp++) {
            if (lp > l) break;
            int fboff = sel4(lp, 0, 128, 416, 736);
            int w     = sel4(lp, 128, 96, 64, 32);
            int ub    = 2 * lp + 1;
            int ubase = d * L1 + lp * lp;
            for (int m = 0; m < ub; m++)
                acc += __ldg(&Ul[ubase + m]) * fb[fboff + m * w + lo + k];
        }
        dst[v] = acc;
    }
}

// ---------------------------------------------------------------------------
// K_edge: fused radial + coupling coefficients + gather + multiply + scatter.
// One warp per edge, 8 warps/block.
// ---------------------------------------------------------------------------
__global__ __launch_bounds__(256) void k_edge(
    const float* __restrict__ r,
    const float* __restrict__ sh0, const float* __restrict__ sh1,
    const float* __restrict__ sh2, const float* __restrict__ sh3,
    const float* __restrict__ Wr0, const float* __restrict__ Wr1,
    const float* __restrict__ Wr2, const float* __restrict__ Wr3,
    const float* __restrict__ U0, const float* __restrict__ U1,
    const float* __restrict__ U2, const float* __restrict__ U3,
    const int* __restrict__ centers, const int* __restrict__ neighbors)
{
    __shared__ float s_sh[8][16];
    __shared__ float s_rb[8][8];
    __shared__ float s_rad[8][320];   // radial_lp full rows: offsets {0,128,224,288}
    __shared__ float s_cc[8][144];    // c_l[d,lp] coeffs: offsets {0,1,7,34}, 142 used

    const int wid  = threadIdx.x >> 5;
    const int lane = threadIdx.x & 31;
    const int e    = blockIdx.x * 8 + wid;
    if (e >= N_EDGES) return;

    const float rv = __ldg(&r[e]);

    // spherical-harmonic values for this edge (16 floats)
    if (lane < 16) {
        float v;
        if (lane == 0)      v = __ldg(&sh0[e]);
        else if (lane < 4)  v = __ldg(&sh1[(size_t)e * 3 + (lane - 1)]);
        else if (lane < 9)  v = __ldg(&sh2[(size_t)e * 5 + (lane - 4)]);
        else                v = __ldg(&sh3[(size_t)e * 7 + (lane - 9)]);
        s_sh[wid][lane] = v;
    }
    // radial basis (8 values) with smooth cutoff
    if (lane < 8) {
        const float PI = 3.14159265358979323846f;
        float fc = 0.5f * (cosf(PI * fminf(rv * 0.2f, 1.0f)) + 1.0f);
        float a  = rv * (PI * 0.2f);
        s_rb[wid][lane] = sinf((float)(lane + 1) * a) / (rv + 1e-6f) * fc;
    }
    __syncwarp();

    // radial[lp][c] = rb . Wrad_lp[:,c], all 320 values
    for (int t = lane; t < 320; t += 32) {
        int lp = (t >= 288) ? 3 : (t >= 224) ? 2 : (t >= 128) ? 1 : 0;
        int c  = t - sel4(lp, 0, 128, 224, 288);
        int w  = sel4(lp, 128, 96, 64, 32);
        const float* W = selp(lp, Wr0, Wr1, Wr2, Wr3);
        float acc = 0.f;
        #pragma unroll
        for (int i = 0; i < 8; i++)
            acc += s_rb[wid][i] * __ldg(&W[i * w + c]);
        s_rad[wid][t] = acc;
    }
    // c_l[d,lp] = sum_m U_l[d, lp^2+m] * sh_lp[m]   (142 values)
    for (int t = lane; t < 142; t += 32) {
        int l   = (t >= 34) ? 3 : (t >= 7) ? 2 : (t >= 1) ? 1 : 0;
        int rem = t - sel4(l, 0, 1, 7, 34);
        int d   = rem / (l + 1);
        int lp  = rem - d * (l + 1);
        const float* Ul = selp(l, U0, U1, U2, U3);
        int ubase = d * (l + 1) * (l + 1) + lp * lp;
        int shoff = lp * lp;   // {0,1,4,9}
        float acc = 0.f;
        int ub = 2 * lp + 1;
        for (int m = 0; m < ub; m++)
            acc += __ldg(&Ul[ubase + m]) * s_sh[wid][shoff + m];
        s_cc[wid][t] = acc;
    }
    __syncwarp();

    const int ctr = __ldg(&centers[e]);
    const int nb  = __ldg(&neighbors[e]);
    const float* fN = g_uncF + (size_t)nb  * UNC_W;
    float*       pC = g_pool + (size_t)ctr * UNC_W;

    #pragma unroll
    for (int j = 0; j < 10; j++) {
        int u  = lane + 32 * j;
        int cbc = u * 4;
        int l  = (cbc >= 416) ? 3 : (cbc >= 128) ? 2 : (cbc >= 32) ? 1 : 0;
        int idx = cbc - sel4(l, 0, 32, 128, 416);
        int d   = idx >> 5;
        int k0  = idx & 31;
        int lo  = sel4(l, 96, 64, 32, 0);

        float4 f4 = __ldg(reinterpret_cast<const float4*>(fN + cbc));

        float u0 = 0.f, u1 = 0.f, u2 = 0.f, u3 = 0.f;
        const float* ccp = &s_cc[wid][sel4(l, 0, 1, 7, 34) + d * (l + 1)];
        #pragma unroll
        for (int lp = 0; lp <= 3; lp++) {
            if (lp > l) break;
            float c = ccp[lp];
            const float* rp = &s_rad[wid][sel4(lp, 0, 128, 224, 288) + lo + k0];
            u0 += c * rp[0]; u1 += c * rp[1]; u2 += c * rp[2]; u3 += c * rp[3];
        }
        red_add_v4(pC + cbc, u0 * f4.x, u1 * f4.y, u2 * f4.z, u3 * f4.w);
    }
}

// ---------------------------------------------------------------------------
// K_couple: couple pooled back into cat layout, write to g_cat (global).
// cat layout per atom (960 floats): offsets {0,128,416,736}, row width KMAX[l],
// entry [l][m][ (lp-l)*32 + k ].
// ---------------------------------------------------------------------------
__global__ __launch_bounds__(128) void k_couple(
    const float* __restrict__ U0, const float* __restrict__ U1,
    const float* __restrict__ U2, const float* __restrict__ U3)
{
    __shared__ float pb[UNC_W];
    const int n = blockIdx.x;
    const int t = threadIdx.x;

    {
        const float4* src = reinterpret_cast<const float4*>(g_pool + (size_t)n * UNC_W);
        for (int u = t; u < UNC_W / 4; u += 128)
            reinterpret_cast<float4*>(pb)[u] = src[u];
    }
    __syncthreads();

    float* dst = g_cat + (size_t)n * CAT_W;
    for (int v = t; v < CAT_W; v += 128) {
        int lp  = (v >= 448) ? 3 : (v >= 160) ? 2 : (v >= 32) ? 1 : 0;
        int rem = v - sel4(lp, 0, 32, 160, 448);
        int mm  = rem >> 5;
        int k   = rem & 31;
        const float* Ul = selp(lp, U0, U1, U2, U3);
        int L1 = (lp + 1) * (lp + 1);
        int D  = sel4(lp, 1, 3, 9, 27);
        int pof = sel4(lp, 0, 32, 128, 416);
        float acc = 0.f;
        for (int d = 0; d < D; d++)
            acc += __ldg(&Ul[d * L1 + mm]) * pb[pof + d * 32 + k];
        int l = (mm >= 9) ? 3 : (mm >= 4) ? 2 : (mm >= 1) ? 1 : 0;
        int m = mm - l * l;
        int K = sel4(l, 128, 96, 64, 32);
        dst[sel4(l, 0, 128, 416, 736) + m * K + (lp - l) * 32 + k] = acc;
    }
}

// ---------------------------------------------------------------------------
// K_gemm<K,NR,OFF_CAT,OFF_OUT>: out_l = feat_l + cat_l @ Wlin_l (+residual).
// Tiled register-blocked SGEMM: BM=64 rows, BN=K cols, BK=16, 256 threads.
// Each thread: 4 x (K/16) accumulators. A rows come from g_cat (strided by
// atom), B = Wlin_l staged in smem, epilogue fuses feat residual.
// ---------------------------------------------------------------------------
template<int K, int NR, int OFF_CAT, size_t OFF_OUT>
__global__ __launch_bounds__(256) void k_gemm(
    const float* __restrict__ W, const float* __restrict__ feat,
    float* __restrict__ out)
{
    constexpr int BM = 64, BK = 16;
    constexpr int TN = K / 16;             // cols per thread (8,6,4,2)
    __shared__ float As[BK][BM + 1];       // A^T tile (pad to dodge conflicts)
    __shared__ float Bs[BK][K];

    const int t    = threadIdx.x;
    const int trow = t >> 4;               // 0..15 : rows trow*4 .. trow*4+3
    const int tcol = t & 15;               // 0..15 : cols tcol*TN ..
    const int row0 = blockIdx.x * BM;

    float acc[4][TN];
    #pragma unroll
    for (int i = 0; i < 4; i++)
        #pragma unroll
        for (int j = 0; j < TN; j++) acc[i][j] = 0.f;

    // per-thread A-load coords: row ra, float4 col ca
    const int ra = t >> 2;                 // 0..63
    const int ca = t & 3;                  // 0..3  (16 floats = 4 float4)
    const int grow = row0 + ra;
    const int atomA = grow / NR;
    const int mA    = grow - atomA * NR;
    const float* arow = (atomA < N_ATOMS)
        ? g_cat + (size_t)atomA * CAT_W + OFF_CAT + mA * K
        : nullptr;

    for (int k0 = 0; k0 < K; k0 += BK) {
        // A tile: 64 x 16, transposed into As
        {
            float4 v = make_float4(0.f, 0.f, 0.f, 0.f);
            if (arow) v = *reinterpret_cast<const float4*>(arow + k0 + ca * 4);
            As[ca * 4 + 0][ra] = v.x;
            As[ca * 4 + 1][ra] = v.y;
            As[ca * 4 + 2][ra] = v.z;
            As[ca * 4 + 3][ra] = v.w;
        }
        // B tile: 16 x K
        {
            constexpr int T4 = BK * K / 4;
            #pragma unroll
            for (int i = t; i < T4; i += 256) {
                int br = i / (K / 4);
                int bc = i - br * (K / 4);
                *reinterpret_cast<float4*>(&Bs[br][bc * 4]) =
                    __ldg(reinterpret_cast<const float4*>(&W[(k0 + br) * K + bc * 4]));
            }
        }
        __syncthreads();

        #pragma unroll
        for (int kk = 0; kk < BK; kk++) {
            float a0 = As[kk][trow * 4 + 0];
            float a1 = As[kk][trow * 4 + 1];
            float a2 = As[kk][trow * 4 + 2];
            float a3 = As[kk][trow * 4 + 3];
            #pragma unroll
            for (int j = 0; j < TN; j++) {
                float b = Bs[kk][tcol * TN + j];
                acc[0][j] += a0 * b;
                acc[1][j] += a1 * b;
                acc[2][j] += a2 * b;
                acc[3][j] += a3 * b;
            }
        }
        __syncthreads();
    }

    // epilogue: residual add + store
    #pragma unroll
    for (int i = 0; i < 4; i++) {
        int grow2 = row0 + trow * 4 + i;
        int atom  = grow2 / NR;
        int m     = grow2 - atom * NR;
        if (atom >= N_ATOMS) continue;
        size_t base = (size_t)atom * NR * K + m * K + tcol * TN;
        const float* fr = feat + base;
        float*       op = out + OFF_OUT + base;
        #pragma unroll
        for (int j = 0; j < TN; j++)
            op[j] = acc[i][j] + __ldg(&fr[j]);
    }
}

// ---------------------------------------------------------------------------
// kernel_launch: robust input binding (see round-4 notes). Detect ordering
// via in_sizes: [0]==1 -> alphabetical; [2]==1280000 -> interleaved dict
// order; else grouped signature order.
// ---------------------------------------------------------------------------
extern "C" void kernel_launch(void* const* d_in, const int* in_sizes, int n_in,
                              void* d_out, int out_size)
{
    int I_r, I_sh[4], I_f[4], I_Wr[4], I_U[4], I_Wl[4], I_c, I_nb;

    if (in_sizes[0] == 1) {
        for (int l = 0; l < 4; l++) { I_U[l] = l; I_Wl[l] = 4 + l; I_Wr[l] = 8 + l; }
        I_c = 12;
        for (int l = 0; l < 4; l++) I_f[l] = 13 + l;
        I_nb = 17; I_r = 18;
        for (int l = 0; l < 4; l++) I_sh[l] = 19 + l;
    } else if (in_sizes[2] == 1280000) {
        I_r = 0;
        for (int l = 0; l < 4; l++) {
            I_sh[l] = 1 + 5 * l; I_f[l]  = 2 + 5 * l; I_Wr[l] = 3 + 5 * l;
            I_U[l]  = 4 + 5 * l; I_Wl[l] = 5 + 5 * l;
        }
        I_c = 21; I_nb = 22;
    } else {
        I_r = 0;
        for (int l = 0; l < 4; l++) {
            I_sh[l] = 1 + l; I_f[l] = 5 + l; I_Wr[l] = 9 + l;
            I_U[l] = 13 + l; I_Wl[l] = 17 + l;
        }
        I_c = 21; I_nb = 22;
    }

    const float* r   = (const float*)d_in[I_r];
    const float* sh0 = (const float*)d_in[I_sh[0]];
    const float* sh1 = (const float*)d_in[I_sh[1]];
    const float* sh2 = (const float*)d_in[I_sh[2]];
    const float* sh3 = (const float*)d_in[I_sh[3]];
    const float* f0  = (const float*)d_in[I_f[0]];
    const float* f1  = (const float*)d_in[I_f[1]];
    const float* f2  = (const float*)d_in[I_f[2]];
    const float* f3  = (const float*)d_in[I_f[3]];
    const float* Wr0 = (const float*)d_in[I_Wr[0]];
    const float* Wr1 = (const float*)d_in[I_Wr[1]];
    const float* Wr2 = (const float*)d_in[I_Wr[2]];
    const float* Wr3 = (const float*)d_in[I_Wr[3]];
    const float* U0  = (const float*)d_in[I_U[0]];
    const float* U1  = (const float*)d_in[I_U[1]];
    const float* U2  = (const float*)d_in[I_U[2]];
    const float* U3  = (const float*)d_in[I_U[3]];
    const float* W0  = (const float*)d_in[I_Wl[0]];
    const float* W1  = (const float*)d_in[I_Wl[1]];
    const float* W2  = (const float*)d_in[I_Wl[2]];
    const float* W3  = (const float*)d_in[I_Wl[3]];
    const int* centers   = (const int*)d_in[I_c];
    const int* neighbors = (const int*)d_in[I_nb];
    float* out = (float*)d_out;

    k_uncf<<<N_ATOMS, 128>>>(f0, f1, f2, f3, U0, U1, U2, U3);
    k_edge<<<(N_EDGES + 7) / 8, 256>>>(r, sh0, sh1, sh2, sh3,
                                       Wr0, Wr1, Wr2, Wr3,
                                       U0, U1, U2, U3, centers, neighbors);
    k_couple<<<N_ATOMS, 128>>>(U0, U1, U2, U3);

    // out_l = feat_l + cat_l @ Wlin_l   (M_l = N_ATOMS*(2l+1) rows)
    k_gemm<128, 1,   0, (size_t)0      ><<<(N_ATOMS * 1 + 63) / 64, 256>>>(W0, f0, out);
    k_gemm< 96, 3, 128, (size_t)1280000><<<(N_ATOMS * 3 + 63) / 64, 256>>>(W1, f1, out);
    k_gemm< 64, 5, 416, (size_t)4160000><<<(N_ATOMS * 5 + 63) / 64, 256>>>(W2, f2, out);
    k_gemm< 32, 7, 736, (size_t)7360000><<<(N_ATOMS * 7 + 63) / 64, 256>>>(W3, f3, out);
}